// round 3
// baseline (speedup 1.0000x reference)
#include <cuda_runtime.h>
#include <cuda_bf16.h>
#include <cstdint>

#define B_    8
#define CIN_  256
#define COUT_ 256
#define L_    32768

// ---------------------------------------------------------------------------
// Device scratch (static __device__ arrays: allocation-free rule)
// ---------------------------------------------------------------------------
__device__ float g_ain[B_ * 512];
__device__ float g_aout[B_ * 512];
__device__ __align__(16) uint32_t g_Whi[B_ * COUT_ * (CIN_ / 2)];  // packed bf16x2, K-major
__device__ __align__(16) uint32_t g_Wlo[B_ * COUT_ * (CIN_ / 2)];

// ---------------------------------------------------------------------------
// Helpers
// ---------------------------------------------------------------------------
__device__ __forceinline__ uint32_t smem_u32(const void* p) {
    uint32_t a;
    asm("{ .reg .u64 t; cvta.to.shared.u64 t, %1; cvt.u32.u64 %0, t; }" : "=r"(a) : "l"(p));
    return a;
}

__device__ __forceinline__ void ldsm4(uint32_t* r, uint32_t addr) {
    asm volatile("ldmatrix.sync.aligned.m8n8.x4.shared.b16 {%0,%1,%2,%3}, [%4];"
                 : "=r"(r[0]), "=r"(r[1]), "=r"(r[2]), "=r"(r[3]) : "r"(addr));
}

__device__ __forceinline__ void mma16816(float* d, const uint32_t* a, const uint32_t* b) {
    asm volatile("mma.sync.aligned.m16n8k16.row.col.f32.bf16.bf16.f32 "
                 "{%0,%1,%2,%3}, {%4,%5,%6,%7}, {%8,%9}, {%0,%1,%2,%3};"
                 : "+f"(d[0]), "+f"(d[1]), "+f"(d[2]), "+f"(d[3])
                 : "r"(a[0]), "r"(a[1]), "r"(a[2]), "r"(a[3]), "r"(b[0]), "r"(b[1]));
}

__device__ __forceinline__ void cp16(uint32_t dst, const void* src) {
    asm volatile("cp.async.cg.shared.global [%0], [%1], 16;" :: "r"(dst), "l"(src));
}
#define CP_COMMIT() asm volatile("cp.async.commit_group;" ::: "memory")

// ---------------------------------------------------------------------------
// Prep 1: a_in[b,k] = W_ain[k,:]·g[b,:]; a_out[b,k] = W_aout[k,:]·g[b,:]
// ---------------------------------------------------------------------------
__global__ void prep_a_kernel(const float* __restrict__ g_out,
                              const float* __restrict__ W_ain,
                              const float* __restrict__ W_aout) {
    __shared__ float g[256];
    int b = blockIdx.x, t = threadIdx.x;
    g[t] = g_out[b * 256 + t];
    __syncthreads();
    for (int rr = 0; rr < 2; rr++) {
        int k = rr * 256 + t;
        const float* w1 = W_ain + (size_t)k * 256;
        const float* w2 = W_aout + (size_t)k * 256;
        float s1 = 0.f, s2 = 0.f;
#pragma unroll 8
        for (int i = 0; i < 256; i++) { s1 += w1[i] * g[i]; s2 += w2[i] * g[i]; }
        g_ain[b * 512 + k] = s1;
        g_aout[b * 512 + k] = s2;
    }
}

// ---------------------------------------------------------------------------
// Prep 2: W_eff[b,o,i] = W_main[o,i] + sum_r a_out[b, r*256+o] * a_in[b, i*2+r]
// split to bf16 hi/lo, packed bf16x2 along K.
// ---------------------------------------------------------------------------
__global__ void prep_w_kernel(const float* __restrict__ W_main) {
    int b = blockIdx.x;
    int idx = blockIdx.y * 256 + threadIdx.x;   // 0..32767 word index
    int o = idx >> 7;
    int p = idx & 127;
    int i = p * 2;
    float ao0 = g_aout[b * 512 + 0 * 256 + o];
    float ao1 = g_aout[b * 512 + 1 * 256 + o];
    float ai00 = g_ain[b * 512 + i * 2 + 0],       ai01 = g_ain[b * 512 + i * 2 + 1];
    float ai10 = g_ain[b * 512 + (i + 1) * 2 + 0], ai11 = g_ain[b * 512 + (i + 1) * 2 + 1];
    float w0 = W_main[(size_t)o * 256 + i]     + ao0 * ai00 + ao1 * ai01;
    float w1 = W_main[(size_t)o * 256 + i + 1] + ao0 * ai10 + ao1 * ai11;
    __nv_bfloat16 h0 = __float2bfloat16_rn(w0);
    __nv_bfloat16 h1 = __float2bfloat16_rn(w1);
    __nv_bfloat16 e0 = __float2bfloat16_rn(w0 - __bfloat162float(h0));
    __nv_bfloat16 e1 = __float2bfloat16_rn(w1 - __bfloat162float(h1));
    uint32_t hi = ((uint32_t)__bfloat16_as_ushort(h1) << 16) | __bfloat16_as_ushort(h0);
    uint32_t lo = ((uint32_t)__bfloat16_as_ushort(e1) << 16) | __bfloat16_as_ushort(e0);
    g_Whi[((size_t)b * 256 + o) * 128 + p] = hi;
    g_Wlo[((size_t)b * 256 + o) * 128 + p] = lo;
}

// ---------------------------------------------------------------------------
// Main GEMM via mma.sync m16n8k16 bf16 (legacy HMMA path; tcgen05 not
// available: harness PTX target is base sm_103).
//
// Per CTA (256 thr): tile 128 L (M) x 256 COUT (N) x K=256 (4 chunks of 64).
// 8 warps = 4 (L) x 2 (C); warp tile 32L x 128C; 128 fp32 accums/thread.
// A = x bf16 hi/lo in SMEM [l][k] swizzled; B = W_eff hi/lo in SMEM [c][k].
// W double-buffered via cp.async; next x chunk prefetched to regs during MMA.
// 3-term split: Xhi*Whi + Xhi*Wlo + Xlo*Whi  (fp32 accumulate).
// ---------------------------------------------------------------------------
#define SM_BIAS 0u
#define SM_XHI  1024u
#define SM_XLO  17408u
#define SM_W    33792u            // 2 stages x (32KB hi + 32KB lo)
#define SM_TOT  164864u

__global__ void __launch_bounds__(256, 1)
lora_main_kernel(const float* __restrict__ x,
                 const float* __restrict__ b_main,
                 float* __restrict__ out) {
    extern __shared__ char smem[];
    uint32_t sb = smem_u32(smem);
    const int t    = threadIdx.x;
    const int lane = t & 31;
    const int wid  = t >> 5;
    const int bx   = blockIdx.x;
    const int b    = bx >> 8;
    const int l0   = (bx & 255) << 7;

    const int wl0 = (wid & 3) * 32;    // warp L base within tile
    const int cb  = (wid >> 2) * 128;  // warp C base

    // bias -> smem
    ((float*)smem)[t] = b_main[t];

    // ---------------- per-thread address precompute ----------------
    const int quad = lane >> 3;
    const int r7   = lane & 7;
    // A (x) ldmatrix: row = wl0 + (quad&1)*8 + r7 (+ mi*16); k-half = quad>>1
    const int a_row = wl0 + (quad & 1) * 8 + r7;
    const uint32_t xhiA = sb + SM_XHI + (uint32_t)a_row * 128u;
    const uint32_t xloA = sb + SM_XLO + (uint32_t)a_row * 128u;
    const int qhA = quad >> 1;
    // B (W) ldmatrix: row = cb + (quad>>1)*8 + r7 (+ nb*16); k-half = quad&1
    const int b_row = cb + (quad >> 1) * 8 + r7;
    const uint32_t wB = sb + SM_W + (uint32_t)b_row * 128u;
    const int qhB = quad & 1;

    // x load/convert mapping: thread owns column l = t&127, k-half = t>>7
    const int xl    = t & 127;
    const int khalf = t >> 7;
    const int xl7   = xl & 7;
    const float* xg = x + (size_t)b * CIN_ * L_ + l0 + xl;
    char* sxhi = smem + SM_XHI + (size_t)xl * 128;
    char* sxlo = smem + SM_XLO + (size_t)xl * 128;

    // W cp.async mapping: 8 passes, row c = pass*32 + (t>>3), seg = t&7
    const uint4* gwh = (const uint4*)g_Whi + (size_t)b * 256 * 32;
    const uint4* gwl = (const uint4*)g_Wlo + (size_t)b * 256 * 32;
    const int wc_r = t >> 3;   // row within pass
    const int wc_s = t & 7;    // 16B segment

    float acc[2][16][4];
#pragma unroll
    for (int i = 0; i < 2; i++)
#pragma unroll
        for (int j = 0; j < 16; j++)
#pragma unroll
            for (int k = 0; k < 4; k++) acc[i][j][k] = 0.f;

    // ---------------- prologue: W chunk0 cp.async, x chunk0 regs ----------
    {
#pragma unroll
        for (int pass = 0; pass < 8; pass++) {
            int c = pass * 32 + wc_r;
            uint32_t dsw = ((uint32_t)(wc_s ^ (c & 7))) << 4;
            uint32_t dst = sb + SM_W + (uint32_t)c * 128u + dsw;
            cp16(dst, gwh + (size_t)c * 32 + 0 * 8 + wc_s);
            cp16(dst + 32768u, gwl + (size_t)c * 32 + 0 * 8 + wc_s);
        }
        CP_COMMIT();
    }
    float v[32];
#pragma unroll
    for (int kk = 0; kk < 32; kk++)
        v[kk] = xg[(size_t)(khalf * 32 + kk) * L_];

    // ---------------- main loop over 4 K-chunks ----------------
#pragma unroll 1
    for (int c = 0; c < 4; c++) {
        const int s = c & 1;

        // issue W chunk c+1 into other stage
        if (c < 3) {
#pragma unroll
            for (int pass = 0; pass < 8; pass++) {
                int cc = pass * 32 + wc_r;
                uint32_t dsw = ((uint32_t)(wc_s ^ (cc & 7))) << 4;
                uint32_t dst = sb + SM_W + (uint32_t)(s ^ 1) * 65536u +
                               (uint32_t)cc * 128u + dsw;
                cp16(dst, gwh + (size_t)cc * 32 + (c + 1) * 8 + wc_s);
                cp16(dst + 32768u, gwl + (size_t)cc * 32 + (c + 1) * 8 + wc_s);
            }
            CP_COMMIT();
        }

        // convert x regs -> bf16 hi/lo SMEM
#pragma unroll
        for (int q = 0; q < 16; q++) {
            float v0 = v[2 * q], v1 = v[2 * q + 1];
            __nv_bfloat16 h0 = __float2bfloat16_rn(v0);
            __nv_bfloat16 h1 = __float2bfloat16_rn(v1);
            __nv_bfloat16 e0 = __float2bfloat16_rn(v0 - __bfloat162float(h0));
            __nv_bfloat16 e1 = __float2bfloat16_rn(v1 - __bfloat162float(h1));
            uint32_t hi = ((uint32_t)__bfloat16_as_ushort(h1) << 16) | __bfloat16_as_ushort(h0);
            uint32_t lo = ((uint32_t)__bfloat16_as_ushort(e1) << 16) | __bfloat16_as_ushort(e0);
            int w = khalf * 16 + q;
            uint32_t off = ((uint32_t)((w >> 2) ^ xl7) << 4) + (uint32_t)(w & 3) * 4;
            *(uint32_t*)(sxhi + off) = hi;
            *(uint32_t*)(sxlo + off) = lo;
        }

        // wait W chunk c resident
        if (c < 3) asm volatile("cp.async.wait_group 1;" ::: "memory");
        else       asm volatile("cp.async.wait_group 0;" ::: "memory");
        __syncthreads();

        // prefetch next x chunk into regs (overlaps MMA)
        if (c < 3) {
#pragma unroll
            for (int kk = 0; kk < 32; kk++)
                v[kk] = xg[(size_t)((c + 1) * 64 + khalf * 32 + kk) * L_];
        }

        // ---------------- MMA phase ----------------
        const uint32_t wHi = wB + (uint32_t)s * 65536u;
        const uint32_t wLo = wHi + 32768u;
#pragma unroll
        for (int ks = 0; ks < 4; ks++) {
            uint32_t ah[8], al[8];
            uint32_t aoff = ((uint32_t)((ks * 2 + qhA) ^ r7)) << 4;
            ldsm4(ah + 0, xhiA + aoff);
            ldsm4(ah + 4, xhiA + 2048u + aoff);
            ldsm4(al + 0, xloA + aoff);
            ldsm4(al + 4, xloA + 2048u + aoff);
            uint32_t boff = ((uint32_t)((ks * 2 + qhB) ^ r7)) << 4;
#pragma unroll
            for (int nb = 0; nb < 8; nb++) {
                uint32_t bh[4], bl[4];
                ldsm4(bh, wHi + (uint32_t)nb * 2048u + boff);
                ldsm4(bl, wLo + (uint32_t)nb * 2048u + boff);
                mma16816(acc[0][2 * nb + 0], ah + 0, bh + 0);
                mma16816(acc[1][2 * nb + 0], ah + 4, bh + 0);
                mma16816(acc[0][2 * nb + 1], ah + 0, bh + 2);
                mma16816(acc[1][2 * nb + 1], ah + 4, bh + 2);
                mma16816(acc[0][2 * nb + 0], ah + 0, bl + 0);
                mma16816(acc[1][2 * nb + 0], ah + 4, bl + 0);
                mma16816(acc[0][2 * nb + 1], ah + 0, bl + 2);
                mma16816(acc[1][2 * nb + 1], ah + 4, bl + 2);
                mma16816(acc[0][2 * nb + 0], al + 0, bh + 0);
                mma16816(acc[1][2 * nb + 0], al + 4, bh + 0);
                mma16816(acc[0][2 * nb + 1], al + 0, bh + 2);
                mma16816(acc[1][2 * nb + 1], al + 4, bh + 2);
            }
        }
        __syncthreads();
    }

    // ---------------- epilogue: direct STG (full 32B sectors) ----------------
    const float* sbias = (const float*)smem;
#pragma unroll
    for (int mi = 0; mi < 2; mi++) {
        int l = l0 + wl0 + mi * 16 + (lane >> 2);
#pragma unroll
        for (int f = 0; f < 16; f++) {
            int c0 = cb + f * 8 + (lane & 3) * 2;
            float bi0 = sbias[c0], bi1 = sbias[c0 + 1];
            float* o0 = out + (size_t)(b * COUT_ + c0) * L_ + l;
            o0[0]       = acc[mi][f][0] + bi0;
            o0[L_]      = acc[mi][f][1] + bi1;
            o0[8]       = acc[mi][f][2] + bi0;
            o0[L_ + 8]  = acc[mi][f][3] + bi1;
        }
    }
}

// ---------------------------------------------------------------------------
// Launch
// ---------------------------------------------------------------------------
extern "C" void kernel_launch(void* const* d_in, const int* in_sizes, int n_in,
                              void* d_out, int out_size) {
    const float* x      = (const float*)d_in[0];
    const float* g_out  = (const float*)d_in[1];
    const float* W_main = (const float*)d_in[2];
    const float* b_main = (const float*)d_in[3];
    const float* W_ain  = (const float*)d_in[4];
    const float* W_aout = (const float*)d_in[5];
    float* out = (float*)d_out;

    prep_a_kernel<<<B_, 256>>>(g_out, W_ain, W_aout);
    prep_w_kernel<<<dim3(B_, 128), 256>>>(W_main);

    cudaFuncSetAttribute(lora_main_kernel,
                         cudaFuncAttributeMaxDynamicSharedMemorySize, SM_TOT);
    lora_main_kernel<<<B_ * (L_ / 128), 256, SM_TOT>>>(x, b_main, out);
}

// round 7
// speedup vs baseline: 2.5917x; 2.5917x over previous
#include <cuda_runtime.h>
#include <cuda_bf16.h>
#include <cstdint>

#define B_    8
#define CIN_  256
#define COUT_ 256
#define L_    32768

// ---------------------------------------------------------------------------
// Device scratch
// ---------------------------------------------------------------------------
__device__ float g_ain[B_ * 512];
__device__ float g_aout[B_ * 512];
__device__ __align__(16) uint32_t g_Whi[B_ * COUT_ * (CIN_ / 2)];  // packed bf16x2, K-major
__device__ __align__(16) uint32_t g_Wlo[B_ * COUT_ * (CIN_ / 2)];

// ---------------------------------------------------------------------------
// Helpers
// ---------------------------------------------------------------------------
__device__ __forceinline__ uint32_t smem_u32(const void* p) {
    uint32_t a;
    asm("{ .reg .u64 t; cvta.to.shared.u64 t, %1; cvt.u32.u64 %0, t; }" : "=r"(a) : "l"(p));
    return a;
}

__device__ __forceinline__ void ldsm4(uint32_t* r, uint32_t addr) {
    asm volatile("ldmatrix.sync.aligned.m8n8.x4.shared.b16 {%0,%1,%2,%3}, [%4];"
                 : "=r"(r[0]), "=r"(r[1]), "=r"(r[2]), "=r"(r[3]) : "r"(addr));
}

__device__ __forceinline__ void mma16816(float* d, const uint32_t* a, const uint32_t* b) {
    asm volatile("mma.sync.aligned.m16n8k16.row.col.f32.bf16.bf16.f32 "
                 "{%0,%1,%2,%3}, {%4,%5,%6,%7}, {%8,%9}, {%0,%1,%2,%3};"
                 : "+f"(d[0]), "+f"(d[1]), "+f"(d[2]), "+f"(d[3])
                 : "r"(a[0]), "r"(a[1]), "r"(a[2]), "r"(a[3]), "r"(b[0]), "r"(b[1]));
}

__device__ __forceinline__ void cp16(uint32_t dst, const void* src) {
    asm volatile("cp.async.cg.shared.global [%0], [%1], 16;" :: "r"(dst), "l"(src));
}
#define CP_COMMIT() asm volatile("cp.async.commit_group;" ::: "memory")

// ---------------------------------------------------------------------------
// Prep 1 (parallel): a_in[b,k] = W_ain[k,:]·g[b,:]; same for a_out.
// grid (B, 4), 256 thr. One warp handles 16 k values, coalesced + shfl reduce.
// ---------------------------------------------------------------------------
__global__ void prep_a_kernel(const float* __restrict__ g_out,
                              const float* __restrict__ W_ain,
                              const float* __restrict__ W_aout) {
    __shared__ float g[256];
    int b = blockIdx.x, t = threadIdx.x;
    int warp = t >> 5, lane = t & 31;
    g[t] = g_out[b * 256 + t];
    __syncthreads();
#pragma unroll 1
    for (int it = 0; it < 16; it++) {
        int k = blockIdx.y * 128 + warp * 16 + it;
        const float* w1 = W_ain + (size_t)k * 256;
        const float* w2 = W_aout + (size_t)k * 256;
        float s1 = 0.f, s2 = 0.f;
#pragma unroll
        for (int j = 0; j < 8; j++) {
            int i = j * 32 + lane;
            s1 += w1[i] * g[i];
            s2 += w2[i] * g[i];
        }
#pragma unroll
        for (int o = 16; o >= 1; o >>= 1) {
            s1 += __shfl_xor_sync(0xFFFFFFFFu, s1, o);
            s2 += __shfl_xor_sync(0xFFFFFFFFu, s2, o);
        }
        if (lane == 0) {
            g_ain[b * 512 + k] = s1;
            g_aout[b * 512 + k] = s2;
        }
    }
}

// ---------------------------------------------------------------------------
// Prep 2: W_eff split to bf16 hi/lo, packed bf16x2 along K.
// ---------------------------------------------------------------------------
__global__ void prep_w_kernel(const float* __restrict__ W_main) {
    int b = blockIdx.x;
    int idx = blockIdx.y * 256 + threadIdx.x;
    int o = idx >> 7;
    int p = idx & 127;
    int i = p * 2;
    float ao0 = g_aout[b * 512 + 0 * 256 + o];
    float ao1 = g_aout[b * 512 + 1 * 256 + o];
    float ai00 = g_ain[b * 512 + i * 2 + 0],       ai01 = g_ain[b * 512 + i * 2 + 1];
    float ai10 = g_ain[b * 512 + (i + 1) * 2 + 0], ai11 = g_ain[b * 512 + (i + 1) * 2 + 1];
    float w0 = W_main[(size_t)o * 256 + i]     + ao0 * ai00 + ao1 * ai01;
    float w1 = W_main[(size_t)o * 256 + i + 1] + ao0 * ai10 + ao1 * ai11;
    __nv_bfloat16 h0 = __float2bfloat16_rn(w0);
    __nv_bfloat16 h1 = __float2bfloat16_rn(w1);
    __nv_bfloat16 e0 = __float2bfloat16_rn(w0 - __bfloat162float(h0));
    __nv_bfloat16 e1 = __float2bfloat16_rn(w1 - __bfloat162float(h1));
    uint32_t hi = ((uint32_t)__bfloat16_as_ushort(h1) << 16) | __bfloat16_as_ushort(h0);
    uint32_t lo = ((uint32_t)__bfloat16_as_ushort(e1) << 16) | __bfloat16_as_ushort(e0);
    g_Whi[((size_t)b * 256 + o) * 128 + p] = hi;
    g_Wlo[((size_t)b * 256 + o) * 128 + p] = lo;
}

// ---------------------------------------------------------------------------
// Main GEMM (mma.sync m16n8k16 bf16, 3-term hi/lo split).
// Per CTA: 64 L x 256 COUT x K=256 (4 chunks of 64). 2 CTAs/SM.
// 8 warps = 2(L) x 4(C); warp tile 32L x 64C; 64 fp32 accums/thread.
// SMEM 81KB: bias 1KB + x hi/lo 16KB + W hi/lo single-buffer 64KB.
// ---------------------------------------------------------------------------
#define SM_XHI  1024u
#define SM_XLO  9216u
#define SM_W    17408u
#define SM_TOT  82944u

__global__ void __launch_bounds__(256, 2)
lora_main_kernel(const float* __restrict__ x,
                 const float* __restrict__ b_main,
                 float* __restrict__ out) {
    extern __shared__ char smem[];
    uint32_t sb = smem_u32(smem);
    const int t    = threadIdx.x;
    const int lane = t & 31;
    const int wid  = t >> 5;
    const int bx   = blockIdx.x;
    const int b    = bx >> 9;
    const int l0   = (bx & 511) << 6;

    const int wl0 = (wid & 1) * 32;    // warp L base
    const int cb  = (wid >> 1) * 64;   // warp C base

    ((float*)smem)[t] = b_main[t];     // bias

    // ---- ldmatrix address precompute ----
    const int quad = lane >> 3;
    const int r7   = lane & 7;
    const int a_row = wl0 + (quad & 1) * 8 + r7;
    const uint32_t xhiA = sb + SM_XHI + (uint32_t)a_row * 128u;
    const uint32_t xloA = sb + SM_XLO + (uint32_t)a_row * 128u;
    const int qhA = quad >> 1;
    const int b_row = cb + (quad >> 1) * 8 + r7;
    const uint32_t wB = sb + SM_W + (uint32_t)b_row * 128u;
    const int qhB = quad & 1;

    // ---- x converter mapping: thread owns l = t&63, k-quarter = t>>6 ----
    const int xl    = t & 63;
    const int kq    = t >> 6;          // 0..3, 16 k each
    const int xl7   = xl & 7;
    const float* xg = x + (size_t)b * CIN_ * L_ + l0 + xl;
    char* sxhi = smem + SM_XHI + (size_t)xl * 128;
    char* sxlo = smem + SM_XLO + (size_t)xl * 128;

    // ---- W cp.async mapping ----
    const uint4* gwh = (const uint4*)g_Whi + (size_t)b * 256 * 32;
    const uint4* gwl = (const uint4*)g_Wlo + (size_t)b * 256 * 32;
    const int wc_r = t >> 3;
    const int wc_s = t & 7;

    float acc[2][8][4];
#pragma unroll
    for (int i = 0; i < 2; i++)
#pragma unroll
        for (int j = 0; j < 8; j++)
#pragma unroll
            for (int k = 0; k < 4; k++) acc[i][j][k] = 0.f;

    // ---- prologue: W chunk0 cp.async; x chunk0 -> regs ----
#pragma unroll
    for (int pass = 0; pass < 8; pass++) {
        int c = pass * 32 + wc_r;
        uint32_t dsw = ((uint32_t)(wc_s ^ (c & 7))) << 4;
        uint32_t dst = sb + SM_W + (uint32_t)c * 128u + dsw;
        cp16(dst, gwh + (size_t)c * 32 + wc_s);
        cp16(dst + 32768u, gwl + (size_t)c * 32 + wc_s);
    }
    CP_COMMIT();
    float v[16];
#pragma unroll
    for (int kk = 0; kk < 16; kk++)
        v[kk] = xg[(size_t)(kq * 16 + kk) * L_];

    // ---- main loop over 4 K-chunks (single-buffered W + x) ----
#pragma unroll 1
    for (int c = 0; c < 4; c++) {
        if (c > 0) {
            // previous sync guarantees buffers are free
#pragma unroll
            for (int pass = 0; pass < 8; pass++) {
                int cc = pass * 32 + wc_r;
                uint32_t dsw = ((uint32_t)(wc_s ^ (cc & 7))) << 4;
                uint32_t dst = sb + SM_W + (uint32_t)cc * 128u + dsw;
                cp16(dst, gwh + (size_t)cc * 32 + c * 8 + wc_s);
                cp16(dst + 32768u, gwl + (size_t)cc * 32 + c * 8 + wc_s);
            }
            CP_COMMIT();
        }

        // convert x regs -> bf16 hi/lo, STS.128 (conflict-free with XOR swizzle)
        uint32_t hw[8], lw[8];
#pragma unroll
        for (int q = 0; q < 8; q++) {
            float v0 = v[2 * q], v1 = v[2 * q + 1];
            __nv_bfloat16 h0 = __float2bfloat16_rn(v0);
            __nv_bfloat16 h1 = __float2bfloat16_rn(v1);
            __nv_bfloat16 e0 = __float2bfloat16_rn(v0 - __bfloat162float(h0));
            __nv_bfloat16 e1 = __float2bfloat16_rn(v1 - __bfloat162float(h1));
            hw[q] = ((uint32_t)__bfloat16_as_ushort(h1) << 16) | __bfloat16_as_ushort(h0);
            lw[q] = ((uint32_t)__bfloat16_as_ushort(e1) << 16) | __bfloat16_as_ushort(e0);
        }
#pragma unroll
        for (int sgi = 0; sgi < 2; sgi++) {
            int seg = kq * 2 + sgi;                    // 16B segment within row
            uint32_t off = ((uint32_t)(seg ^ xl7)) << 4;
            *(uint4*)(sxhi + off) = make_uint4(hw[4*sgi], hw[4*sgi+1], hw[4*sgi+2], hw[4*sgi+3]);
            *(uint4*)(sxlo + off) = make_uint4(lw[4*sgi], lw[4*sgi+1], lw[4*sgi+2], lw[4*sgi+3]);
        }

        asm volatile("cp.async.wait_group 0;" ::: "memory");
        __syncthreads();

        // prefetch next x chunk (overlaps MMA)
        if (c < 3) {
#pragma unroll
            for (int kk = 0; kk < 16; kk++)
                v[kk] = xg[(size_t)((c + 1) * 64 + kq * 16 + kk) * L_];
        }

        // ---- MMA phase ----
#pragma unroll
        for (int ks = 0; ks < 4; ks++) {
            uint32_t ah[8], al[8];
            uint32_t aoff = ((uint32_t)((ks * 2 + qhA) ^ r7)) << 4;
            ldsm4(ah + 0, xhiA + aoff);
            ldsm4(ah + 4, xhiA + 2048u + aoff);
            ldsm4(al + 0, xloA + aoff);
            ldsm4(al + 4, xloA + 2048u + aoff);
            uint32_t boff = ((uint32_t)((ks * 2 + qhB) ^ r7)) << 4;
#pragma unroll
            for (int g = 0; g < 4; g++) {
                uint32_t bh[4], bl[4];
                ldsm4(bh, wB + (uint32_t)g * 2048u + boff);
                ldsm4(bl, wB + 32768u + (uint32_t)g * 2048u + boff);
                mma16816(acc[0][2 * g + 0], ah + 0, bh + 0);
                mma16816(acc[1][2 * g + 0], ah + 4, bh + 0);
                mma16816(acc[0][2 * g + 1], ah + 0, bh + 2);
                mma16816(acc[1][2 * g + 1], ah + 4, bh + 2);
                mma16816(acc[0][2 * g + 0], ah + 0, bl + 0);
                mma16816(acc[1][2 * g + 0], ah + 4, bl + 0);
                mma16816(acc[0][2 * g + 1], ah + 0, bl + 2);
                mma16816(acc[1][2 * g + 1], ah + 4, bl + 2);
                mma16816(acc[0][2 * g + 0], al + 0, bh + 0);
                mma16816(acc[1][2 * g + 0], al + 4, bh + 0);
                mma16816(acc[0][2 * g + 1], al + 0, bh + 2);
                mma16816(acc[1][2 * g + 1], al + 4, bh + 2);
            }
        }
        __syncthreads();
    }

    // ---- epilogue: direct STG, coalesced 64B runs per (c,l16) ----
    const float* sbias = (const float*)smem;
#pragma unroll
    for (int mi = 0; mi < 2; mi++) {
        int l = l0 + wl0 + mi * 16 + (lane >> 2);
#pragma unroll
        for (int f = 0; f < 8; f++) {
            int c0 = cb + f * 8 + (lane & 3) * 2;
            float bi0 = sbias[c0], bi1 = sbias[c0 + 1];
            float* o0 = out + (size_t)(b * COUT_ + c0) * L_ + l;
            o0[0]       = acc[mi][f][0] + bi0;
            o0[L_]      = acc[mi][f][1] + bi1;
            o0[8]       = acc[mi][f][2] + bi0;
            o0[L_ + 8]  = acc[mi][f][3] + bi1;
        }
    }
}

// ---------------------------------------------------------------------------
// Launch
// ---------------------------------------------------------------------------
extern "C" void kernel_launch(void* const* d_in, const int* in_sizes, int n_in,
                              void* d_out, int out_size) {
    const float* x      = (const float*)d_in[0];
    const float* g_out  = (const float*)d_in[1];
    const float* W_main = (const float*)d_in[2];
    const float* b_main = (const float*)d_in[3];
    const float* W_ain  = (const float*)d_in[4];
    const float* W_aout = (const float*)d_in[5];
    float* out = (float*)d_out;

    prep_a_kernel<<<dim3(B_, 4), 256>>>(g_out, W_ain, W_aout);
    prep_w_kernel<<<dim3(B_, 128), 256>>>(W_main);

    cudaFuncSetAttribute(lora_main_kernel,
                         cudaFuncAttributeMaxDynamicSharedMemorySize, SM_TOT);
    lora_main_kernel<<<B_ * (L_ / 64), 256, SM_TOT>>>(x, b_main, out);
}

// round 12
// speedup vs baseline: 2.8542x; 1.1013x over previous
#include <cuda_runtime.h>
#include <cuda_bf16.h>
#include <cstdint>

#define B_    8
#define CIN_  256
#define COUT_ 256
#define L_    32768

// ---------------------------------------------------------------------------
// Device scratch
// ---------------------------------------------------------------------------
__device__ float g_ain[B_ * 512];
__device__ float g_aout[B_ * 512];
__device__ __align__(16) uint32_t g_Whi[B_ * COUT_ * (CIN_ / 2)];  // packed bf16x2, K-major
__device__ __align__(16) uint32_t g_Wlo[B_ * COUT_ * (CIN_ / 2)];

// ---------------------------------------------------------------------------
// Helpers
// ---------------------------------------------------------------------------
__device__ __forceinline__ uint32_t smem_u32(const void* p) {
    uint32_t a;
    asm("{ .reg .u64 t; cvta.to.shared.u64 t, %1; cvt.u32.u64 %0, t; }" : "=r"(a) : "l"(p));
    return a;
}

__device__ __forceinline__ void ldsm4(uint32_t* r, uint32_t addr) {
    asm volatile("ldmatrix.sync.aligned.m8n8.x4.shared.b16 {%0,%1,%2,%3}, [%4];"
                 : "=r"(r[0]), "=r"(r[1]), "=r"(r[2]), "=r"(r[3]) : "r"(addr));
}

__device__ __forceinline__ void mma16816(float* d, const uint32_t* a, const uint32_t* b) {
    asm volatile("mma.sync.aligned.m16n8k16.row.col.f32.bf16.bf16.f32 "
                 "{%0,%1,%2,%3}, {%4,%5,%6,%7}, {%8,%9}, {%0,%1,%2,%3};"
                 : "+f"(d[0]), "+f"(d[1]), "+f"(d[2]), "+f"(d[3])
                 : "r"(a[0]), "r"(a[1]), "r"(a[2]), "r"(a[3]), "r"(b[0]), "r"(b[1]));
}

__device__ __forceinline__ void cp16(uint32_t dst, const void* src) {
    asm volatile("cp.async.cg.shared.global [%0], [%1], 16;" :: "r"(dst), "l"(src));
}
#define CP_COMMIT() asm volatile("cp.async.commit_group;" ::: "memory")

// ---------------------------------------------------------------------------
// Prep 1: a_in[b,k] = W_ain[k,:]·g[b,:]; a_out[b,k] = W_aout[k,:]·g[b,:]
// grid (B, 16), 8 warps/block, 4 k per warp -> 512 warps/batch total work.
// ---------------------------------------------------------------------------
__global__ void prep_a_kernel(const float* __restrict__ g_out,
                              const float* __restrict__ W_ain,
                              const float* __restrict__ W_aout) {
    __shared__ float g[256];
    int b = blockIdx.x, t = threadIdx.x;
    int warp = t >> 5, lane = t & 31;
    g[t] = g_out[b * 256 + t];
    __syncthreads();
    int wg = blockIdx.y * 8 + warp;          // 0..127
#pragma unroll
    for (int it = 0; it < 4; it++) {
        int k = wg * 4 + it;                 // 0..511
        const float* w1 = W_ain + (size_t)k * 256;
        const float* w2 = W_aout + (size_t)k * 256;
        float s1 = 0.f, s2 = 0.f;
#pragma unroll
        for (int j = 0; j < 8; j++) {
            int i = j * 32 + lane;
            s1 += w1[i] * g[i];
            s2 += w2[i] * g[i];
        }
#pragma unroll
        for (int o = 16; o >= 1; o >>= 1) {
            s1 += __shfl_xor_sync(0xFFFFFFFFu, s1, o);
            s2 += __shfl_xor_sync(0xFFFFFFFFu, s2, o);
        }
        if (lane == 0) {
            g_ain[b * 512 + k] = s1;
            g_aout[b * 512 + k] = s2;
        }
    }
}

// ---------------------------------------------------------------------------
// Prep 2: W_eff split to bf16 hi/lo, packed bf16x2 along K.
// ---------------------------------------------------------------------------
__global__ void prep_w_kernel(const float* __restrict__ W_main) {
    int b = blockIdx.x;
    int idx = blockIdx.y * 256 + threadIdx.x;
    int o = idx >> 7;
    int p = idx & 127;
    int i = p * 2;
    float ao0 = g_aout[b * 512 + 0 * 256 + o];
    float ao1 = g_aout[b * 512 + 1 * 256 + o];
    float ai00 = g_ain[b * 512 + i * 2 + 0],       ai01 = g_ain[b * 512 + i * 2 + 1];
    float ai10 = g_ain[b * 512 + (i + 1) * 2 + 0], ai11 = g_ain[b * 512 + (i + 1) * 2 + 1];
    float w0 = W_main[(size_t)o * 256 + i]     + ao0 * ai00 + ao1 * ai01;
    float w1 = W_main[(size_t)o * 256 + i + 1] + ao0 * ai10 + ao1 * ai11;
    __nv_bfloat16 h0 = __float2bfloat16_rn(w0);
    __nv_bfloat16 h1 = __float2bfloat16_rn(w1);
    __nv_bfloat16 e0 = __float2bfloat16_rn(w0 - __bfloat162float(h0));
    __nv_bfloat16 e1 = __float2bfloat16_rn(w1 - __bfloat162float(h1));
    uint32_t hi = ((uint32_t)__bfloat16_as_ushort(h1) << 16) | __bfloat16_as_ushort(h0);
    uint32_t lo = ((uint32_t)__bfloat16_as_ushort(e1) << 16) | __bfloat16_as_ushort(e0);
    g_Whi[((size_t)b * 256 + o) * 128 + p] = hi;
    g_Wlo[((size_t)b * 256 + o) * 128 + p] = lo;
}

// ---------------------------------------------------------------------------
// Main GEMM (mma.sync m16n8k16 bf16, 3-term hi/lo split), pipelined.
// Per CTA: 64 L x 256 COUT x K=256 in 8 chunks of K=32. 2 CTAs/SM.
// 8 warps = 2(L) x 4(C); warp tile 32L x 64C; 64 fp32 accums/thread.
// SMEM 81KB: bias 1KB; x hi/lo 2 stages x 8KB; W hi/lo 2 stages x 32KB.
// Rows are 64B (32 k bf16); swizzle: seg' = seg ^ ((row>>1)&3).
// Per chunk: convert x -> stage, wait W, sync, issue next W cp.async + x LDG,
// MMA. W load overlaps the previous chunk's whole MMA phase.
// ---------------------------------------------------------------------------
#define SM_X    1024u              // 2 stages x (hi 4KB + lo 4KB)
#define SM_W    17408u             // 2 stages x (hi 16KB + lo 16KB)
#define SM_TOT  82944u

__global__ void __launch_bounds__(256, 2)
lora_main_kernel(const float* __restrict__ x,
                 const float* __restrict__ b_main,
                 float* __restrict__ out) {
    extern __shared__ char smem[];
    uint32_t sb = smem_u32(smem);
    const int t    = threadIdx.x;
    const int lane = t & 31;
    const int wid  = t >> 5;
    const int bx   = blockIdx.x;
    const int b    = bx >> 9;
    const int l0   = (bx & 511) << 6;

    const int wl0 = (wid & 1) * 32;    // warp L base
    const int cb  = (wid >> 1) * 64;   // warp C base

    ((float*)smem)[t] = b_main[t];     // bias

    // ---- ldmatrix address precompute ----
    const int quad = lane >> 3;
    const int r7   = lane & 7;
    const int a_row = wl0 + (quad & 1) * 8 + r7;
    const uint32_t aswz = ((uint32_t)a_row >> 1) & 3u;
    const uint32_t xA   = sb + SM_X + (uint32_t)a_row * 64u;
    const int qhA = quad >> 1;
    const int b_row = cb + (quad >> 1) * 8 + r7;
    const uint32_t bswz = ((uint32_t)b_row >> 1) & 3u;
    const uint32_t wBb  = sb + SM_W + (uint32_t)b_row * 64u;
    const int qhB = quad & 1;

    // ---- x converter mapping: thread owns l = t&63, k-seg kq = t>>6 ----
    const int xl = t & 63;
    const int kq = t >> 6;             // 0..3, 8 k each
    const float* xg = x + (size_t)b * CIN_ * L_ + l0 + xl;
    char* sxh = smem + SM_X + (size_t)xl * 64 +
                (size_t)((kq ^ ((xl >> 1) & 3)) << 4);

    // ---- W cp.async mapping: 4 passes x (o = p*64 + t>>2, seg = t&3) ----
    const uint4* gwh = (const uint4*)g_Whi + (size_t)b * 256 * 32;
    const uint4* gwl = (const uint4*)g_Wlo + (size_t)b * 256 * 32;
    const int wo   = t >> 2;
    const int wseg = t & 3;
    const uint32_t wdst0 = (uint32_t)wo * 64u +
                           ((uint32_t)(wseg ^ ((wo >> 1) & 3)) << 4);

    float acc[2][8][4];
#pragma unroll
    for (int i = 0; i < 2; i++)
#pragma unroll
        for (int j = 0; j < 8; j++)
#pragma unroll
            for (int k = 0; k < 4; k++) acc[i][j][k] = 0.f;

    // ---- prologue: W chunk0 cp.async into stage0; x chunk0 -> regs ----
    {
        uint32_t wsb = sb + SM_W + wdst0;
#pragma unroll
        for (int p = 0; p < 4; p++) {
            size_t gi = (size_t)(p * 64 + wo) * 32 + wseg;  // chunk 0: +0
            cp16(wsb + p * 4096u, gwh + gi);
            cp16(wsb + 16384u + p * 4096u, gwl + gi);
        }
        CP_COMMIT();
    }
    float v[8];
#pragma unroll
    for (int kk = 0; kk < 8; kk++)
        v[kk] = xg[(size_t)(kq * 8 + kk) * L_];

    // ---- main loop over 8 K-chunks ----
#pragma unroll 1
    for (int c = 0; c < 8; c++) {
        const int st = c & 1;

        // convert x regs -> bf16 hi/lo, one STS.128 each (conflict-free)
        {
            uint32_t hw[4], lw[4];
#pragma unroll
            for (int q = 0; q < 4; q++) {
                float v0 = v[2 * q], v1 = v[2 * q + 1];
                __nv_bfloat16 h0 = __float2bfloat16_rn(v0);
                __nv_bfloat16 h1 = __float2bfloat16_rn(v1);
                __nv_bfloat16 e0 = __float2bfloat16_rn(v0 - __bfloat162float(h0));
                __nv_bfloat16 e1 = __float2bfloat16_rn(v1 - __bfloat162float(h1));
                hw[q] = ((uint32_t)__bfloat16_as_ushort(h1) << 16) | __bfloat16_as_ushort(h0);
                lw[q] = ((uint32_t)__bfloat16_as_ushort(e1) << 16) | __bfloat16_as_ushort(e0);
            }
            char* d = sxh + st * 8192;
            *(uint4*)d            = make_uint4(hw[0], hw[1], hw[2], hw[3]);
            *(uint4*)(d + 4096)   = make_uint4(lw[0], lw[1], lw[2], lw[3]);
        }

        // chunk c's W (issued one MMA-phase ago) must be resident
        asm volatile("cp.async.wait_group 0;" ::: "memory");
        __syncthreads();

        if (c < 7) {
            // issue W chunk c+1 into the stage freed by MMA(c-1)
            uint32_t wsb = sb + SM_W + (uint32_t)(st ^ 1) * 32768u + wdst0;
#pragma unroll
            for (int p = 0; p < 4; p++) {
                size_t gi = (size_t)(p * 64 + wo) * 32 + (c + 1) * 4 + wseg;
                cp16(wsb + p * 4096u, gwh + gi);
                cp16(wsb + 16384u + p * 4096u, gwl + gi);
            }
            CP_COMMIT();
            // prefetch next x chunk (overlaps MMA)
#pragma unroll
            for (int kk = 0; kk < 8; kk++)
                v[kk] = xg[(size_t)((c + 1) * 32 + kq * 8 + kk) * L_];
        }

        // ---- MMA phase (chunk c: 2 k-steps of 16) ----
        const uint32_t xhiS = xA + (uint32_t)st * 8192u;
        const uint32_t xloS = xhiS + 4096u;
        const uint32_t wS   = wBb + (uint32_t)st * 32768u;
#pragma unroll
        for (int ks = 0; ks < 2; ks++) {
            uint32_t ah[8], al[8];
            uint32_t aoff = ((uint32_t)(ks * 2 + qhA) ^ aswz) << 4;
            ldsm4(ah + 0, xhiS + aoff);
            ldsm4(ah + 4, xhiS + 1024u + aoff);
            ldsm4(al + 0, xloS + aoff);
            ldsm4(al + 4, xloS + 1024u + aoff);
            uint32_t boff = ((uint32_t)(ks * 2 + qhB) ^ bswz) << 4;
#pragma unroll
            for (int g = 0; g < 4; g++) {
                uint32_t bh[4], bl[4];
                ldsm4(bh, wS + (uint32_t)g * 1024u + boff);
                ldsm4(bl, wS + 16384u + (uint32_t)g * 1024u + boff);
                mma16816(acc[0][2 * g + 0], ah + 0, bh + 0);
                mma16816(acc[1][2 * g + 0], ah + 4, bh + 0);
                mma16816(acc[0][2 * g + 1], ah + 0, bh + 2);
                mma16816(acc[1][2 * g + 1], ah + 4, bh + 2);
                mma16816(acc[0][2 * g + 0], ah + 0, bl + 0);
                mma16816(acc[1][2 * g + 0], ah + 4, bl + 0);
                mma16816(acc[0][2 * g + 1], ah + 0, bl + 2);
                mma16816(acc[1][2 * g + 1], ah + 4, bl + 2);
                mma16816(acc[0][2 * g + 0], al + 0, bh + 0);
                mma16816(acc[1][2 * g + 0], al + 4, bh + 0);
                mma16816(acc[0][2 * g + 1], al + 0, bh + 2);
                mma16816(acc[1][2 * g + 1], al + 4, bh + 2);
            }
        }
    }

    // ---- epilogue: direct STG (full 32B sectors per channel run) ----
    const float* sbias = (const float*)smem;
#pragma unroll
    for (int mi = 0; mi < 2; mi++) {
        int l = l0 + wl0 + mi * 16 + (lane >> 2);
#pragma unroll
        for (int f = 0; f < 8; f++) {
            int c0 = cb + f * 8 + (lane & 3) * 2;
            float bi0 = sbias[c0], bi1 = sbias[c0 + 1];
            float* o0 = out + (size_t)(b * COUT_ + c0) * L_ + l;
            o0[0]       = acc[mi][f][0] + bi0;
            o0[L_]      = acc[mi][f][1] + bi1;
            o0[8]       = acc[mi][f][2] + bi0;
            o0[L_ + 8]  = acc[mi][f][3] + bi1;
        }
    }
}

// ---------------------------------------------------------------------------
// Launch
// ---------------------------------------------------------------------------
extern "C" void kernel_launch(void* const* d_in, const int* in_sizes, int n_in,
                              void* d_out, int out_size) {
    const float* x      = (const float*)d_in[0];
    const float* g_out  = (const float*)d_in[1];
    const float* W_main = (const float*)d_in[2];
    const float* b_main = (const float*)d_in[3];
    const float* W_ain  = (const float*)d_in[4];
    const float* W_aout = (const float*)d_in[5];
    float* out = (float*)d_out;

    prep_a_kernel<<<dim3(B_, 16), 256>>>(g_out, W_ain, W_aout);
    prep_w_kernel<<<dim3(B_, 128), 256>>>(W_main);

    cudaFuncSetAttribute(lora_main_kernel,
                         cudaFuncAttributeMaxDynamicSharedMemorySize, SM_TOT);
    lora_main_kernel<<<B_ * (L_ / 64), 256, SM_TOT>>>(x, b_main, out);
}

// round 15
// speedup vs baseline: 4.9236x; 1.7250x over previous
#include <cuda_runtime.h>
#include <cuda_bf16.h>
#include <cuda_fp16.h>
#include <cstdint>

#define B_    8
#define CIN_  256
#define COUT_ 256
#define L_    32768

// ---------------------------------------------------------------------------
// Device scratch
// ---------------------------------------------------------------------------
__device__ float g_ain[B_ * 512];
__device__ float g_aout[B_ * 512];
__device__ __align__(16) uint32_t g_Wh[B_ * COUT_ * (CIN_ / 2)];   // packed fp16x2, K-major

// ---------------------------------------------------------------------------
// Helpers
// ---------------------------------------------------------------------------
__device__ __forceinline__ uint32_t smem_u32(const void* p) {
    uint32_t a;
    asm("{ .reg .u64 t; cvta.to.shared.u64 t, %1; cvt.u32.u64 %0, t; }" : "=r"(a) : "l"(p));
    return a;
}

__device__ __forceinline__ void ldsm4(uint32_t* r, uint32_t addr) {
    asm volatile("ldmatrix.sync.aligned.m8n8.x4.shared.b16 {%0,%1,%2,%3}, [%4];"
                 : "=r"(r[0]), "=r"(r[1]), "=r"(r[2]), "=r"(r[3]) : "r"(addr));
}

__device__ __forceinline__ void mma16816(float* d, const uint32_t* a, const uint32_t* b) {
    asm volatile("mma.sync.aligned.m16n8k16.row.col.f32.f16.f16.f32 "
                 "{%0,%1,%2,%3}, {%4,%5,%6,%7}, {%8,%9}, {%0,%1,%2,%3};"
                 : "+f"(d[0]), "+f"(d[1]), "+f"(d[2]), "+f"(d[3])
                 : "r"(a[0]), "r"(a[1]), "r"(a[2]), "r"(a[3]), "r"(b[0]), "r"(b[1]));
}

__device__ __forceinline__ void cp16(uint32_t dst, const void* src) {
    asm volatile("cp.async.cg.shared.global [%0], [%1], 16;" :: "r"(dst), "l"(src));
}
#define CP_COMMIT() asm volatile("cp.async.commit_group;" ::: "memory")

// ---------------------------------------------------------------------------
// Prep 1: a_in[b,k] = W_ain[k,:]·g[b,:]; a_out[b,k] = W_aout[k,:]·g[b,:]
// grid (B, 32), 8 warps/block, 2 k per warp.
// ---------------------------------------------------------------------------
__global__ void prep_a_kernel(const float* __restrict__ g_out,
                              const float* __restrict__ W_ain,
                              const float* __restrict__ W_aout) {
    __shared__ float g[256];
    int b = blockIdx.x, t = threadIdx.x;
    int warp = t >> 5, lane = t & 31;
    g[t] = g_out[b * 256 + t];
    __syncthreads();
    int wg = blockIdx.y * 8 + warp;          // 0..255
#pragma unroll
    for (int it = 0; it < 2; it++) {
        int k = wg * 2 + it;                 // 0..511
        const float* w1 = W_ain + (size_t)k * 256;
        const float* w2 = W_aout + (size_t)k * 256;
        float s1 = 0.f, s2 = 0.f;
#pragma unroll
        for (int j = 0; j < 8; j++) {
            int i = j * 32 + lane;
            s1 += w1[i] * g[i];
            s2 += w2[i] * g[i];
        }
#pragma unroll
        for (int o = 16; o >= 1; o >>= 1) {
            s1 += __shfl_xor_sync(0xFFFFFFFFu, s1, o);
            s2 += __shfl_xor_sync(0xFFFFFFFFu, s2, o);
        }
        if (lane == 0) {
            g_ain[b * 512 + k] = s1;
            g_aout[b * 512 + k] = s2;
        }
    }
}

// ---------------------------------------------------------------------------
// Prep 2: W_eff -> packed fp16x2 along K.
// ---------------------------------------------------------------------------
__global__ void prep_w_kernel(const float* __restrict__ W_main) {
    int b = blockIdx.x;
    int idx = blockIdx.y * 256 + threadIdx.x;
    int o = idx >> 7;
    int p = idx & 127;
    int i = p * 2;
    float ao0 = g_aout[b * 512 + 0 * 256 + o];
    float ao1 = g_aout[b * 512 + 1 * 256 + o];
    float ai00 = g_ain[b * 512 + i * 2 + 0],       ai01 = g_ain[b * 512 + i * 2 + 1];
    float ai10 = g_ain[b * 512 + (i + 1) * 2 + 0], ai11 = g_ain[b * 512 + (i + 1) * 2 + 1];
    float w0 = W_main[(size_t)o * 256 + i]     + ao0 * ai00 + ao1 * ai01;
    float w1 = W_main[(size_t)o * 256 + i + 1] + ao0 * ai10 + ao1 * ai11;
    __half2 h = __floats2half2_rn(w0, w1);
    g_Wh[((size_t)b * 256 + o) * 128 + p] = *(const uint32_t*)&h;
}

// ---------------------------------------------------------------------------
// Main GEMM (mma.sync m16n8k16 fp16, single term, fp32 accumulate).
// Per CTA: 64 L x 256 COUT x K=256 in 8 chunks of K=32. 2 CTAs/SM.
// 8 warps = 2(L) x 4(C); warp tile 32L x 64C; 64 fp32 accums/thread.
// SMEM 41KB: bias 1KB; x 2 stages x 4KB; W 2 stages x 16KB.
// Rows are 64B (32 k fp16); swizzle: seg' = seg ^ ((row>>1)&3).
// Per chunk: convert x -> stage, wait W, sync, issue next W cp.async + x LDG,
// MMA. W load overlaps the previous chunk's whole MMA phase.
// ---------------------------------------------------------------------------
#define SM_X    1024u              // 2 stages x 4KB
#define SM_W    9216u              // 2 stages x 16KB
#define SM_TOT  41984u

__global__ void __launch_bounds__(256, 2)
lora_main_kernel(const float* __restrict__ x,
                 const float* __restrict__ b_main,
                 float* __restrict__ out) {
    extern __shared__ char smem[];
    uint32_t sb = smem_u32(smem);
    const int t    = threadIdx.x;
    const int lane = t & 31;
    const int wid  = t >> 5;
    const int bx   = blockIdx.x;
    const int b    = bx >> 9;
    const int l0   = (bx & 511) << 6;

    const int wl0 = (wid & 1) * 32;    // warp L base
    const int cb  = (wid >> 1) * 64;   // warp C base

    ((float*)smem)[t] = b_main[t];     // bias

    // ---- ldmatrix address precompute ----
    const int quad = lane >> 3;
    const int r7   = lane & 7;
    const int a_row = wl0 + (quad & 1) * 8 + r7;
    const uint32_t aswz = ((uint32_t)a_row >> 1) & 3u;
    const uint32_t xA   = sb + SM_X + (uint32_t)a_row * 64u;
    const int qhA = quad >> 1;
    const int b_row = cb + (quad >> 1) * 8 + r7;
    const uint32_t bswz = ((uint32_t)b_row >> 1) & 3u;
    const uint32_t wBb  = sb + SM_W + (uint32_t)b_row * 64u;
    const int qhB = quad & 1;

    // ---- x converter mapping: thread owns l = t&63, k-seg kq = t>>6 ----
    const int xl = t & 63;
    const int kq = t >> 6;             // 0..3, 8 k each
    const float* xg = x + (size_t)b * CIN_ * L_ + l0 + xl;
    char* sxh = smem + SM_X + (size_t)xl * 64 +
                (size_t)((kq ^ ((xl >> 1) & 3)) << 4);

    // ---- W cp.async mapping: 4 passes x (o = p*64 + t>>2, seg = t&3) ----
    const uint4* gwh = (const uint4*)g_Wh + (size_t)b * 256 * 32;
    const int wo   = t >> 2;
    const int wseg = t & 3;
    const uint32_t wdst0 = (uint32_t)wo * 64u +
                           ((uint32_t)(wseg ^ ((wo >> 1) & 3)) << 4);

    float acc[2][8][4];
#pragma unroll
    for (int i = 0; i < 2; i++)
#pragma unroll
        for (int j = 0; j < 8; j++)
#pragma unroll
            for (int k = 0; k < 4; k++) acc[i][j][k] = 0.f;

    // ---- prologue: W chunk0 cp.async into stage0; x chunk0 -> regs ----
    {
        uint32_t wsb = sb + SM_W + wdst0;
#pragma unroll
        for (int p = 0; p < 4; p++) {
            size_t gi = (size_t)(p * 64 + wo) * 32 + wseg;  // chunk 0
            cp16(wsb + p * 4096u, gwh + gi);
        }
        CP_COMMIT();
    }
    float v[8];
#pragma unroll
    for (int kk = 0; kk < 8; kk++)
        v[kk] = xg[(size_t)(kq * 8 + kk) * L_];

    // ---- main loop over 8 K-chunks ----
#pragma unroll 1
    for (int c = 0; c < 8; c++) {
        const int st = c & 1;

        // convert x regs -> fp16, one STS.128 (conflict-free)
        {
            uint32_t hw[4];
#pragma unroll
            for (int q = 0; q < 4; q++) {
                __half2 h = __floats2half2_rn(v[2 * q], v[2 * q + 1]);
                hw[q] = *(const uint32_t*)&h;
            }
            *(uint4*)(sxh + st * 4096) = make_uint4(hw[0], hw[1], hw[2], hw[3]);
        }

        // chunk c's W (issued one MMA-phase ago) must be resident
        asm volatile("cp.async.wait_group 0;" ::: "memory");
        __syncthreads();

        if (c < 7) {
            // issue W chunk c+1 into the stage freed by MMA(c-1)
            uint32_t wsb = sb + SM_W + (uint32_t)(st ^ 1) * 16384u + wdst0;
#pragma unroll
            for (int p = 0; p < 4; p++) {
                size_t gi = (size_t)(p * 64 + wo) * 32 + (c + 1) * 4 + wseg;
                cp16(wsb + p * 4096u, gwh + gi);
            }
            CP_COMMIT();
            // prefetch next x chunk (overlaps MMA)
#pragma unroll
            for (int kk = 0; kk < 8; kk++)
                v[kk] = xg[(size_t)((c + 1) * 32 + kq * 8 + kk) * L_];
        }

        // ---- MMA phase (chunk c: 2 k-steps of 16) ----
        const uint32_t xS = xA + (uint32_t)st * 4096u;
        const uint32_t wS = wBb + (uint32_t)st * 16384u;
#pragma unroll
        for (int ks = 0; ks < 2; ks++) {
            uint32_t ah[8];
            uint32_t aoff = ((uint32_t)(ks * 2 + qhA) ^ aswz) << 4;
            ldsm4(ah + 0, xS + aoff);
            ldsm4(ah + 4, xS + 1024u + aoff);
            uint32_t boff = ((uint32_t)(ks * 2 + qhB) ^ bswz) << 4;
#pragma unroll
            for (int g = 0; g < 4; g++) {
                uint32_t bh[4];
                ldsm4(bh, wS + (uint32_t)g * 1024u + boff);
                mma16816(acc[0][2 * g + 0], ah + 0, bh + 0);
                mma16816(acc[1][2 * g + 0], ah + 4, bh + 0);
                mma16816(acc[0][2 * g + 1], ah + 0, bh + 2);
                mma16816(acc[1][2 * g + 1], ah + 4, bh + 2);
            }
        }
    }

    // ---- epilogue: direct STG (full 32B sectors per channel run) ----
    const float* sbias = (const float*)smem;
#pragma unroll
    for (int mi = 0; mi < 2; mi++) {
        int l = l0 + wl0 + mi * 16 + (lane >> 2);
#pragma unroll
        for (int f = 0; f < 8; f++) {
            int c0 = cb + f * 8 + (lane & 3) * 2;
            float bi0 = sbias[c0], bi1 = sbias[c0 + 1];
            float* o0 = out + (size_t)(b * COUT_ + c0) * L_ + l;
            o0[0]       = acc[mi][f][0] + bi0;
            o0[L_]      = acc[mi][f][1] + bi1;
            o0[8]       = acc[mi][f][2] + bi0;
            o0[L_ + 8]  = acc[mi][f][3] + bi1;
        }
    }
}

// ---------------------------------------------------------------------------
// Launch
// ---------------------------------------------------------------------------
extern "C" void kernel_launch(void* const* d_in, const int* in_sizes, int n_in,
                              void* d_out, int out_size) {
    const float* x      = (const float*)d_in[0];
    const float* g_out  = (const float*)d_in[1];
    const float* W_main = (const float*)d_in[2];
    const float* b_main = (const float*)d_in[3];
    const float* W_ain  = (const float*)d_in[4];
    const float* W_aout = (const float*)d_in[5];
    float* out = (float*)d_out;

    prep_a_kernel<<<dim3(B_, 32), 256>>>(g_out, W_ain, W_aout);
    prep_w_kernel<<<dim3(B_, 128), 256>>>(W_main);

    cudaFuncSetAttribute(lora_main_kernel,
                         cudaFuncAttributeMaxDynamicSharedMemorySize, SM_TOT);
    lora_main_kernel<<<B_ * (L_ / 64), 256, SM_TOT>>>(x, b_main, out);
}

// round 17
// speedup vs baseline: 5.1745x; 1.0510x over previous
#include <cuda_runtime.h>
#include <cuda_bf16.h>
#include <cuda_fp16.h>
#include <cstdint>

#define B_    8
#define CIN_  256
#define COUT_ 256
#define L_    32768

// ---------------------------------------------------------------------------
// Device scratch
// ---------------------------------------------------------------------------
__device__ float g_ain[B_ * 512];
__device__ float g_aout[B_ * 512];
__device__ __align__(16) uint32_t g_Wh[B_ * COUT_ * (CIN_ / 2)];   // packed fp16x2, K-major

// ---------------------------------------------------------------------------
// Helpers
// ---------------------------------------------------------------------------
__device__ __forceinline__ uint32_t smem_u32(const void* p) {
    uint32_t a;
    asm("{ .reg .u64 t; cvta.to.shared.u64 t, %1; cvt.u32.u64 %0, t; }" : "=r"(a) : "l"(p));
    return a;
}

__device__ __forceinline__ void ldsm4(uint32_t* r, uint32_t addr) {
    asm volatile("ldmatrix.sync.aligned.m8n8.x4.shared.b16 {%0,%1,%2,%3}, [%4];"
                 : "=r"(r[0]), "=r"(r[1]), "=r"(r[2]), "=r"(r[3]) : "r"(addr));
}

__device__ __forceinline__ void mma16816(float* d, const uint32_t* a, const uint32_t* b) {
    asm volatile("mma.sync.aligned.m16n8k16.row.col.f32.f16.f16.f32 "
                 "{%0,%1,%2,%3}, {%4,%5,%6,%7}, {%8,%9}, {%0,%1,%2,%3};"
                 : "+f"(d[0]), "+f"(d[1]), "+f"(d[2]), "+f"(d[3])
                 : "r"(a[0]), "r"(a[1]), "r"(a[2]), "r"(a[3]), "r"(b[0]), "r"(b[1]));
}

__device__ __forceinline__ void cp16(uint32_t dst, const void* src) {
    asm volatile("cp.async.cg.shared.global [%0], [%1], 16;" :: "r"(dst), "l"(src));
}
#define CP_COMMIT() asm volatile("cp.async.commit_group;" ::: "memory")
#define CP_WAIT0()  asm volatile("cp.async.wait_group 0;" ::: "memory")

// ---------------------------------------------------------------------------
// Prep 1: a_in[b,k] = W_ain[k,:]·g[b,:]; a_out[b,k] = W_aout[k,:]·g[b,:]
// grid (B, 64), 8 warps/block, 1 k per warp.
// ---------------------------------------------------------------------------
__global__ void prep_a_kernel(const float* __restrict__ g_out,
                              const float* __restrict__ W_ain,
                              const float* __restrict__ W_aout) {
    __shared__ float g[256];
    int b = blockIdx.x, t = threadIdx.x;
    int warp = t >> 5, lane = t & 31;
    g[t] = g_out[b * 256 + t];
    __syncthreads();
    int k = blockIdx.y * 8 + warp;           // 0..511
    const float* w1 = W_ain + (size_t)k * 256;
    const float* w2 = W_aout + (size_t)k * 256;
    float s1 = 0.f, s2 = 0.f;
#pragma unroll
    for (int j = 0; j < 8; j++) {
        int i = j * 32 + lane;
        s1 += w1[i] * g[i];
        s2 += w2[i] * g[i];
    }
#pragma unroll
    for (int o = 16; o >= 1; o >>= 1) {
        s1 += __shfl_xor_sync(0xFFFFFFFFu, s1, o);
        s2 += __shfl_xor_sync(0xFFFFFFFFu, s2, o);
    }
    if (lane == 0) {
        g_ain[b * 512 + k] = s1;
        g_aout[b * 512 + k] = s2;
    }
}

// ---------------------------------------------------------------------------
// Prep 2: W_eff -> packed fp16x2 along K.
// ---------------------------------------------------------------------------
__global__ void prep_w_kernel(const float* __restrict__ W_main) {
    int b = blockIdx.x;
    int idx = blockIdx.y * 256 + threadIdx.x;
    int o = idx >> 7;
    int p = idx & 127;
    int i = p * 2;
    float ao0 = g_aout[b * 512 + 0 * 256 + o];
    float ao1 = g_aout[b * 512 + 1 * 256 + o];
    float ai00 = g_ain[b * 512 + i * 2 + 0],       ai01 = g_ain[b * 512 + i * 2 + 1];
    float ai10 = g_ain[b * 512 + (i + 1) * 2 + 0], ai11 = g_ain[b * 512 + (i + 1) * 2 + 1];
    float w0 = W_main[(size_t)o * 256 + i]     + ao0 * ai00 + ao1 * ai01;
    float w1 = W_main[(size_t)o * 256 + i + 1] + ao0 * ai10 + ao1 * ai11;
    __half2 h = __floats2half2_rn(w0, w1);
    g_Wh[((size_t)b * 256 + o) * 128 + p] = *(const uint32_t*)&h;
}

// ---------------------------------------------------------------------------
// Main GEMM (mma.sync m16n8k16 fp16, fp32 accumulate), depth-2 x pipeline.
// Per CTA: 64 L x 256 COUT x K=256 in 8 chunks of K=32. 2 CTAs/SM.
// 8 warps = 2(L) x 4(C); warp tile 32L x 64C; 64 fp32 accums/thread.
// SMEM 41KB: bias 1KB; x 2 stages x 4KB; W 2 stages x 16KB.
// Loop unrolled x2 (even chunk uses va/stage0, odd uses vb/stage1):
//   convert v -> stage, wait W(c), sync, issue W(c+1), LDG x(c+2) -> v, MMA(c)
// x LDG now has ~2 chunk bodies of cover -> DRAM latency hidden.
// ---------------------------------------------------------------------------
#define SM_X    1024u              // 2 stages x 4KB
#define SM_W    9216u              // 2 stages x 16KB
#define SM_TOT  41984u

struct MmaCtx {
    uint32_t xA, wBb;       // per-thread ldmatrix row bases
    uint32_t aswz, bswz;
    uint32_t qhA, qhB;
};

__device__ __forceinline__ void convert_x(const float* v, char* dst) {
    uint32_t hw[4];
#pragma unroll
    for (int q = 0; q < 4; q++) {
        __half2 h = __floats2half2_rn(v[2 * q], v[2 * q + 1]);
        hw[q] = *(const uint32_t*)&h;
    }
    *(uint4*)dst = make_uint4(hw[0], hw[1], hw[2], hw[3]);
}

__device__ __forceinline__ void mma_phase(float acc[2][8][4], const MmaCtx& m, int st) {
    const uint32_t xS = m.xA + (uint32_t)st * 4096u;
    const uint32_t wS = m.wBb + (uint32_t)st * 16384u;
#pragma unroll
    for (int ks = 0; ks < 2; ks++) {
        uint32_t ah[8];
        uint32_t aoff = ((uint32_t)(ks * 2 + m.qhA) ^ m.aswz) << 4;
        ldsm4(ah + 0, xS + aoff);
        ldsm4(ah + 4, xS + 1024u + aoff);
        uint32_t boff = ((uint32_t)(ks * 2 + m.qhB) ^ m.bswz) << 4;
#pragma unroll
        for (int g = 0; g < 4; g++) {
            uint32_t bh[4];
            ldsm4(bh, wS + (uint32_t)g * 1024u + boff);
            mma16816(acc[0][2 * g + 0], ah + 0, bh + 0);
            mma16816(acc[1][2 * g + 0], ah + 4, bh + 0);
            mma16816(acc[0][2 * g + 1], ah + 0, bh + 2);
            mma16816(acc[1][2 * g + 1], ah + 4, bh + 2);
        }
    }
}

__global__ void __launch_bounds__(256, 2)
lora_main_kernel(const float* __restrict__ x,
                 const float* __restrict__ b_main,
                 float* __restrict__ out) {
    extern __shared__ char smem[];
    uint32_t sb = smem_u32(smem);
    const int t    = threadIdx.x;
    const int lane = t & 31;
    const int wid  = t >> 5;
    const int bx   = blockIdx.x;
    const int b    = bx >> 9;
    const int l0   = (bx & 511) << 6;

    const int wl0 = (wid & 1) * 32;    // warp L base
    const int cb  = (wid >> 1) * 64;   // warp C base

    ((float*)smem)[t] = b_main[t];     // bias

    // ---- ldmatrix address precompute ----
    MmaCtx m;
    const int quad = lane >> 3;
    const int r7   = lane & 7;
    const int a_row = wl0 + (quad & 1) * 8 + r7;
    m.aswz = ((uint32_t)a_row >> 1) & 3u;
    m.xA   = sb + SM_X + (uint32_t)a_row * 64u;
    m.qhA  = quad >> 1;
    const int b_row = cb + (quad >> 1) * 8 + r7;
    m.bswz = ((uint32_t)b_row >> 1) & 3u;
    m.wBb  = sb + SM_W + (uint32_t)b_row * 64u;
    m.qhB  = quad & 1;

    // ---- x converter mapping: thread owns l = t&63, k-seg kq = t>>6 ----
    const int xl = t & 63;
    const int kq = t >> 6;             // 0..3, 8 k each
    const float* xg = x + (size_t)b * CIN_ * L_ + l0 + xl;
    char* sxh = smem + SM_X + (size_t)xl * 64 +
                (size_t)((kq ^ ((xl >> 1) & 3)) << 4);

    // ---- W cp.async mapping: 4 passes x (o = p*64 + t>>2, seg = t&3) ----
    const uint4* gwh = (const uint4*)g_Wh + (size_t)b * 256 * 32;
    const int wo   = t >> 2;
    const int wseg = t & 3;
    const uint32_t wdst0 = (uint32_t)wo * 64u +
                           ((uint32_t)(wseg ^ ((wo >> 1) & 3)) << 4);

    float acc[2][8][4];
#pragma unroll
    for (int i = 0; i < 2; i++)
#pragma unroll
        for (int j = 0; j < 8; j++)
#pragma unroll
            for (int k = 0; k < 4; k++) acc[i][j][k] = 0.f;

    // ---- prologue: W chunk0 cp.async; x chunks 0,1 -> regs ----
    {
        uint32_t wsb = sb + SM_W + wdst0;
#pragma unroll
        for (int p = 0; p < 4; p++) {
            size_t gi = (size_t)(p * 64 + wo) * 32 + wseg;  // chunk 0
            cp16(wsb + p * 4096u, gwh + gi);
        }
        CP_COMMIT();
    }
    float va[8], vb[8];
#pragma unroll
    for (int kk = 0; kk < 8; kk++)
        va[kk] = xg[(size_t)(kq * 8 + kk) * L_];
#pragma unroll
    for (int kk = 0; kk < 8; kk++)
        vb[kk] = xg[(size_t)(32 + kq * 8 + kk) * L_];

    // ---- main loop: 4 iterations, 2 chunks each ----
#pragma unroll 1
    for (int cc = 0; cc < 4; cc++) {
        const int c0 = cc * 2;

        // ===== even chunk c0 (stage 0, va) =====
        convert_x(va, sxh);
        CP_WAIT0();                     // W(c0) resident
        __syncthreads();
        {   // issue W(c0+1) into stage 1
            uint32_t wsb = sb + SM_W + 16384u + wdst0;
#pragma unroll
            for (int p = 0; p < 4; p++) {
                size_t gi = (size_t)(p * 64 + wo) * 32 + (c0 + 1) * 4 + wseg;
                cp16(wsb + p * 4096u, gwh + gi);
            }
            CP_COMMIT();
        }
        if (c0 + 2 < 8) {               // LDG x(c0+2) -> va (2-chunk cover)
#pragma unroll
            for (int kk = 0; kk < 8; kk++)
                va[kk] = xg[(size_t)((c0 + 2) * 32 + kq * 8 + kk) * L_];
        }
        mma_phase(acc, m, 0);

        // ===== odd chunk c0+1 (stage 1, vb) =====
        convert_x(vb, sxh + 4096);
        CP_WAIT0();                     // W(c0+1) resident
        __syncthreads();
        if (c0 + 2 < 8) {               // issue W(c0+2) into stage 0
            uint32_t wsb = sb + SM_W + wdst0;
#pragma unroll
            for (int p = 0; p < 4; p++) {
                size_t gi = (size_t)(p * 64 + wo) * 32 + (c0 + 2) * 4 + wseg;
                cp16(wsb + p * 4096u, gwh + gi);
            }
            CP_COMMIT();
        }
        if (c0 + 3 < 8) {               // LDG x(c0+3) -> vb
#pragma unroll
            for (int kk = 0; kk < 8; kk++)
                vb[kk] = xg[(size_t)((c0 + 3) * 32 + kq * 8 + kk) * L_];
        }
        mma_phase(acc, m, 1);
    }

    // ---- epilogue: direct STG (full 32B sectors per channel run) ----
    const float* sbias = (const float*)smem;
#pragma unroll
    for (int mi = 0; mi < 2; mi++) {
        int l = l0 + wl0 + mi * 16 + (lane >> 2);
#pragma unroll
        for (int f = 0; f < 8; f++) {
            int c0 = cb + f * 8 + (lane & 3) * 2;
            float bi0 = sbias[c0], bi1 = sbias[c0 + 1];
            float* o0 = out + (size_t)(b * COUT_ + c0) * L_ + l;
            o0[0]       = acc[mi][f][0] + bi0;
            o0[L_]      = acc[mi][f][1] + bi1;
            o0[8]       = acc[mi][f][2] + bi0;
            o0[L_ + 8]  = acc[mi][f][3] + bi1;
        }
    }
}

// ---------------------------------------------------------------------------
// Launch
// ---------------------------------------------------------------------------
extern "C" void kernel_launch(void* const* d_in, const int* in_sizes, int n_in,
                              void* d_out, int out_size) {
    const float* x      = (const float*)d_in[0];
    const float* g_out  = (const float*)d_in[1];
    const float* W_main = (const float*)d_in[2];
    const float* b_main = (const float*)d_in[3];
    const float* W_ain  = (const float*)d_in[4];
    const float* W_aout = (const float*)d_in[5];
    float* out = (float*)d_out;

    prep_a_kernel<<<dim3(B_, 64), 256>>>(g_out, W_ain, W_aout);
    prep_w_kernel<<<dim3(B_, 128), 256>>>(W_main);

    cudaFuncSetAttribute(lora_main_kernel,
                         cudaFuncAttributeMaxDynamicSharedMemorySize, SM_TOT);
    lora_main_kernel<<<B_ * (L_ / 64), 256, SM_TOT>>>(x, b_main, out);
}